// round 11
// baseline (speedup 1.0000x reference)
#include <cuda_runtime.h>
#include <cstdint>

#define BB 64
#define PP 1024
#define TT 1024
#define NITER 50
#define HALFP 512      // p-rows per cluster CTA

// bf16 Gibbs kernel, layout [b][p][t], t contiguous. 134 MB.
__device__ __align__(16) unsigned short g_Kb[(size_t)BB * PP * TT];
__device__ __align__(16) float g_u[BB * PP];
__device__ __align__(16) float g_v[BB * TT];

__device__ __forceinline__ unsigned int bf16pair(float a, float b) {
    unsigned int ua = __float_as_uint(a);
    unsigned int ub = __float_as_uint(b);
    ua = (ua + 0x7FFFu + ((ua >> 16) & 1u)) >> 16;   // RN-even
    ub = (ub + 0x7FFFu + ((ub >> 16) & 1u)) >> 16;
    return ua | (ub << 16);
}
// bf16x2 word -> two f32 (alu-pipe: SHF + LOP3)
__device__ __forceinline__ float bf_lo(unsigned int h) { return __int_as_float(h << 16); }
__device__ __forceinline__ float bf_hi(unsigned int h) { return __int_as_float(h & 0xFFFF0000u); }

// K = exp(-C/reg) -> bf16, 8 elems/thread.
__global__ void k_exp(const float* __restrict__ C, const float* __restrict__ reg) {
    const size_t i8 = (size_t)blockIdx.x * 256 + threadIdx.x;
    const float ninv = -1.0f / reg[0];
    const float4* __restrict__ C4 = (const float4*)C;
    const float4 a = C4[2 * i8];
    const float4 c = C4[2 * i8 + 1];
    uint4 pack;
    pack.x = bf16pair(__expf(a.x * ninv), __expf(a.y * ninv));
    pack.y = bf16pair(__expf(a.z * ninv), __expf(a.w * ninv));
    pack.z = bf16pair(__expf(c.x * ninv), __expf(c.y * ninv));
    pack.w = bf16pair(__expf(c.z * ninv), __expf(c.w * ninv));
    ((uint4*)g_Kb)[i8] = pack;
}

// Persistent fused Sinkhorn, cluster of 2 CTAs per batch (128 CTAs).
// One K pass per iteration. K converted ONCE per row into 32 live f32 regs
// (scalar path, not packed), then used for both dot and accumulate.
__global__ void __launch_bounds__(512, 1) __cluster_dims__(2, 1, 1)
k_sinkhorn(const float* __restrict__ pred, const float* __restrict__ tgt) {
    __shared__ float v_s[TT];             //  4 KB
    __shared__ float u_s[HALFP];          //  2 KB
    __shared__ float buf[8][TT];          // 32 KB warp-combine tree
    __shared__ float part_peer[2][TT];    //  8 KB DSMEM partials (parity)
    __shared__ float pred_s[HALFP];       //  2 KB

    const int tid  = threadIdx.x;
    const int b    = blockIdx.x >> 1;
    const int r    = blockIdx.x & 1;
    const int peer = r ^ 1;
    const int wid  = tid >> 5;
    const int lane = tid & 31;

    pred_s[tid] = pred[b * PP + r * HALFP + tid];
    const float tgt_a = tgt[b * TT + tid];
    const float tgt_b = tgt[b * TT + tid + 512];
    __syncthreads();

    const uint4* __restrict__ K4 =
        (const uint4*)(g_Kb + ((size_t)b * PP + (size_t)r * HALFP) * TT);
    const size_t row0 = (size_t)(wid * 32) * 128;   // uint4 index of warp's row 0

    for (int iter = 0; iter <= NITER; iter++) {
        // v into registers; lane's t-positions: t = 8*(lane+32*i)+j
        float vreg[32];
        if (iter > 0) {
            const float4* __restrict__ vs4 = (const float4*)v_s;
#pragma unroll
            for (int i = 0; i < 4; i++) {
                const float4 va = vs4[2 * (lane + 32 * i) + 0];
                const float4 vb = vs4[2 * (lane + 32 * i) + 1];
                vreg[8*i+0]=va.x; vreg[8*i+1]=va.y; vreg[8*i+2]=va.z; vreg[8*i+3]=va.w;
                vreg[8*i+4]=vb.x; vreg[8*i+5]=vb.y; vreg[8*i+6]=vb.z; vreg[8*i+7]=vb.w;
            }
        }

        float acc[32];
#pragma unroll
        for (int j = 0; j < 32; j++) acc[j] = 0.0f;

        // prefetch row 0
        uint4 k4[4];
#pragma unroll
        for (int i = 0; i < 4; i++) k4[i] = K4[row0 + lane + 32 * i];

#pragma unroll 1
        for (int rr = 0; rr < 32; rr++) {
            uint4 kn[4];
            if (rr < 31) {                 // prefetch next row
                const size_t nrow = row0 + (size_t)(rr + 1) * 128;
#pragma unroll
                for (int i = 0; i < 4; i++) kn[i] = K4[nrow + lane + 32 * i];
            }

            // convert ONCE into live f32 regs (alu pipe: SHF/LOP3)
            const unsigned int* hw = (const unsigned int*)k4;  // 16 bf16x2 words
            float f[32];
#pragma unroll
            for (int q = 0; q < 16; q++) {
                f[2*q+0] = bf_lo(hw[q]);
                f[2*q+1] = bf_hi(hw[q]);
            }

            if (iter == 0) {
                // u = 1: accumulate K directly
#pragma unroll
                for (int j = 0; j < 32; j++)
                    acc[j] += f[j];
            } else {
                // dot(K_p, v): two chains
                float a0 = 0.f, a1 = 0.f;
#pragma unroll
                for (int j = 0; j < 16; j++) {
                    a0 += f[j]      * vreg[j];
                    a1 += f[j + 16] * vreg[j + 16];
                }
                float a = a0 + a1;
#pragma unroll
                for (int o = 16; o; o >>= 1)
                    a += __shfl_xor_sync(0xFFFFFFFFu, a, o);

                const int p = wid * 32 + rr;
                const float up = __fdividef(pred_s[p], a);
                if (iter == NITER && lane == 0) u_s[p] = up;

                // accumulate u_p * K_p from live regs (no reconvert)
#pragma unroll
                for (int j = 0; j < 32; j++)
                    acc[j] += up * f[j];
            }
#pragma unroll
            for (int i = 0; i < 4; i++) k4[i] = kn[i];
        }

        // combine 16 warps -> buf[8][TT] (two rounds)
        if (wid < 8) {
            float4* __restrict__ dst = (float4*)&buf[wid][0];
#pragma unroll
            for (int i = 0; i < 4; i++) {
                const int idx = lane + 32 * i;
                dst[2*idx+0] = make_float4(acc[8*i+0], acc[8*i+1], acc[8*i+2], acc[8*i+3]);
                dst[2*idx+1] = make_float4(acc[8*i+4], acc[8*i+5], acc[8*i+6], acc[8*i+7]);
            }
        }
        __syncthreads();
        if (wid >= 8) {
            float4* __restrict__ dst = (float4*)&buf[wid - 8][0];
#pragma unroll
            for (int i = 0; i < 4; i++) {
                const int idx = lane + 32 * i;
                float4 x = dst[2*idx+0];
                x.x += acc[8*i+0]; x.y += acc[8*i+1]; x.z += acc[8*i+2]; x.w += acc[8*i+3];
                dst[2*idx+0] = x;
                float4 y = dst[2*idx+1];
                y.x += acc[8*i+4]; y.y += acc[8*i+5]; y.z += acc[8*i+6]; y.w += acc[8*i+7];
                dst[2*idx+1] = y;
            }
        }
        __syncthreads();

        float s0 = 0.0f, s1 = 0.0f;
#pragma unroll
        for (int k = 0; k < 8; k++) {
            s0 += buf[k][tid];
            s1 += buf[k][tid + 512];
        }

        // DSMEM exchange with peer CTA (parity double-buffer)
        const int par = iter & 1;
        {
            unsigned int l0 = (unsigned int)__cvta_generic_to_shared(&part_peer[par][tid]);
            unsigned int l1 = (unsigned int)__cvta_generic_to_shared(&part_peer[par][tid + 512]);
            unsigned int r0, r1;
            asm volatile("mapa.shared::cluster.u32 %0, %1, %2;" : "=r"(r0) : "r"(l0), "r"(peer));
            asm volatile("mapa.shared::cluster.u32 %0, %1, %2;" : "=r"(r1) : "r"(l1), "r"(peer));
            asm volatile("st.shared::cluster.f32 [%0], %1;" :: "r"(r0), "f"(s0) : "memory");
            asm volatile("st.shared::cluster.f32 [%0], %1;" :: "r"(r1), "f"(s1) : "memory");
        }
        asm volatile("barrier.cluster.arrive.aligned;" ::: "memory");
        asm volatile("barrier.cluster.wait.aligned;" ::: "memory");

        v_s[tid]       = tgt_a / (s0 + part_peer[par][tid]);
        v_s[tid + 512] = tgt_b / (s1 + part_peer[par][tid + 512]);
        __syncthreads();
    }

    g_u[b * PP + r * HALFP + tid] = u_s[tid];
    if (r == 0) {
        g_v[b * TT + tid]       = v_s[tid];
        g_v[b * TT + tid + 512] = v_s[tid + 512];
    }
}

// Final: P = u * exp(-C/reg) * v recomputed in fp32 from C
// (output never touches bf16 K). float4, 4 elems/thread.
__global__ void k_final(const float* __restrict__ C, const float* __restrict__ reg,
                        float* __restrict__ out) {
    const size_t i4 = (size_t)blockIdx.x * 256 + threadIdx.x;  // float4 index
    const float ninv = -1.0f / reg[0];
    const int row = (int)((i4 * 4) >> 10);     // b*1024 + p
    const int b   = row >> 10;
    const int t4  = (int)(i4 & 255);

    const float  u = g_u[row];
    const float4 c = ((const float4*)C)[i4];
    const float4 v = ((const float4*)(g_v + b * TT))[t4];

    float4 rv;
    rv.x = u * __expf(c.x * ninv) * v.x;
    rv.y = u * __expf(c.y * ninv) * v.y;
    rv.z = u * __expf(c.z * ninv) * v.z;
    rv.w = u * __expf(c.w * ninv) * v.w;
    ((float4*)out)[i4] = rv;
}

extern "C" void kernel_launch(void* const* d_in, const int* in_sizes, int n_in,
                              void* d_out, int out_size) {
    const float* pred = (const float*)d_in[0];
    const float* tgt  = (const float*)d_in[1];
    const float* C    = (const float*)d_in[2];
    const float* reg  = (const float*)d_in[3];
    float* out = (float*)d_out;

    const int n8 = (BB * PP * TT) / 8;
    const int n4 = (BB * PP * TT) / 4;

    k_exp<<<n8 / 256, 256>>>(C, reg);
    k_sinkhorn<<<2 * BB, 512>>>(pred, tgt);
    k_final<<<n4 / 256, 256>>>(C, reg, out);
}